// round 1
// baseline (speedup 1.0000x reference)
#include <cuda_runtime.h>
#include <cuda_bf16.h>

#define N_NODES 100000
#define N_EDGES 1600000
#define FNODE   32
#define FGLOB   16
#define HDIM    64
#define OUTDIM  64

#define SCAN_BS 1024
#define N_SCAN_BLOCKS ((N_NODES + SCAN_BS - 1) / SCAN_BS)   // 98

// ---------------- scratch (device globals: no allocations allowed) ----------
__device__ int   g_cnt[N_NODES];
__device__ int   g_cursor[N_NODES];
__device__ int   g_rowoff[N_NODES + 1];
__device__ int   g_bsum[N_SCAN_BLOCKS];
__device__ int   g_csr[N_EDGES];
__device__ float g_dis[N_NODES];
__device__ float g_h[(size_t)N_NODES * HDIM];
__device__ float g_hw[(size_t)N_NODES * HDIM];
__device__ float g_pool[HDIM];

// ---------------- init: zero counters, cursors, pool ------------------------
__global__ void k_init() {
    int i = blockIdx.x * blockDim.x + threadIdx.x;
    if (i < N_NODES) { g_cnt[i] = 0; g_cursor[i] = 0; }
    if (i < HDIM) g_pool[i] = 0.f;
}

// ---------------- degree count over dst --------------------------------------
__global__ void k_count(const int* __restrict__ dst) {
    int e = blockIdx.x * blockDim.x + threadIdx.x;
    if (e < N_EDGES) atomicAdd(&g_cnt[dst[e]], 1);
}

// ---------------- dis = rsqrt(deg), deg = cnt + 1 (self loop) ----------------
__global__ void k_dis() {
    int i = blockIdx.x * blockDim.x + threadIdx.x;
    if (i < N_NODES) g_dis[i] = rsqrtf((float)(g_cnt[i] + 1));
}

// ---------------- scan stage 1: per-block exclusive scan ---------------------
__global__ void k_scan1() {
    __shared__ int sh[SCAN_BS];
    int tid = threadIdx.x;
    int i = blockIdx.x * SCAN_BS + tid;
    int v = (i < N_NODES) ? g_cnt[i] : 0;
    sh[tid] = v;
    __syncthreads();
    #pragma unroll
    for (int off = 1; off < SCAN_BS; off <<= 1) {
        int t = 0;
        if (tid >= off) t = sh[tid - off];
        __syncthreads();
        if (tid >= off) sh[tid] += t;
        __syncthreads();
    }
    if (i < N_NODES) g_rowoff[i] = sh[tid] - v;   // block-local exclusive
    if (tid == SCAN_BS - 1) g_bsum[blockIdx.x] = sh[tid];
}

// ---------------- scan stage 2: scan the block sums (single block) -----------
__global__ void k_scan2() {
    __shared__ int sh[128];
    int tid = threadIdx.x;
    int v = (tid < N_SCAN_BLOCKS) ? g_bsum[tid] : 0;
    sh[tid] = v;
    __syncthreads();
    #pragma unroll
    for (int off = 1; off < 128; off <<= 1) {
        int t = 0;
        if (tid >= off) t = sh[tid - off];
        __syncthreads();
        if (tid >= off) sh[tid] += t;
        __syncthreads();
    }
    if (tid < N_SCAN_BLOCKS) g_bsum[tid] = sh[tid] - v;  // exclusive
    if (tid == 127) g_rowoff[N_NODES] = sh[127];         // total == N_EDGES
}

// ---------------- scan stage 3: add block offsets ----------------------------
__global__ void k_scan3() {
    int i = blockIdx.x * blockDim.x + threadIdx.x;
    if (i < N_NODES) g_rowoff[i] += g_bsum[i >> 10];
}

// ---------------- CSR fill ----------------------------------------------------
__global__ void k_fill(const int* __restrict__ src, const int* __restrict__ dst) {
    int e = blockIdx.x * blockDim.x + threadIdx.x;
    if (e < N_EDGES) {
        int d = dst[e];
        int pos = g_rowoff[d] + atomicAdd(&g_cursor[d], 1);
        g_csr[pos] = src[e];
    }
}

// ---------------- dense GEMM: out[N,64] = in[N,K] @ W[K,64] (+bias) ----------
// Each thread computes 2 rows x 32 cols in registers; W staged in SMEM.
template<int K, bool BIAS>
__global__ void k_gemm(const float* __restrict__ in, const float* __restrict__ w,
                       const float* __restrict__ bias, float* __restrict__ out) {
    __shared__ float Ws[K * HDIM];
    __shared__ float Bs[HDIM];
    int tid = threadIdx.x;
    for (int j = tid; j < K * HDIM; j += blockDim.x) Ws[j] = w[j];
    if (BIAS && tid < HDIM) Bs[tid] = bias[tid];
    __syncthreads();

    int colBase = (tid & 1) * 32;
    int pair = tid >> 1;                       // 0..127
    int r0 = blockIdx.x * 256 + pair * 2;
    if (r0 >= N_NODES) return;
    bool v1 = (r0 + 1 < N_NODES);

    float acc0[32], acc1[32];
    #pragma unroll
    for (int c = 0; c < 32; c++) { acc0[c] = 0.f; acc1[c] = 0.f; }

    const float4* xr0 = reinterpret_cast<const float4*>(in + (size_t)r0 * K);
    const float4* xr1 = reinterpret_cast<const float4*>(in + (size_t)(v1 ? r0 + 1 : r0) * K);

    #pragma unroll 4
    for (int k4 = 0; k4 < K / 4; ++k4) {
        float4 a = __ldg(&xr0[k4]);
        float4 b = __ldg(&xr1[k4]);
        const float av[4] = {a.x, a.y, a.z, a.w};
        const float bv[4] = {b.x, b.y, b.z, b.w};
        #pragma unroll
        for (int kk = 0; kk < 4; ++kk) {
            const float* wrow = &Ws[(k4 * 4 + kk) * HDIM + colBase];
            float xa = av[kk], xb = bv[kk];
            #pragma unroll
            for (int c = 0; c < 32; c++) {
                float wv = wrow[c];
                acc0[c] += xa * wv;
                acc1[c] += xb * wv;
            }
        }
    }

    if (BIAS) {
        #pragma unroll
        for (int c = 0; c < 32; c++) { acc0[c] += Bs[colBase + c]; acc1[c] += Bs[colBase + c]; }
    }

    float4* o0 = reinterpret_cast<float4*>(out + (size_t)r0 * HDIM + colBase);
    #pragma unroll
    for (int c4 = 0; c4 < 8; c4++)
        o0[c4] = make_float4(acc0[4*c4], acc0[4*c4+1], acc0[4*c4+2], acc0[4*c4+3]);
    if (v1) {
        float4* o1 = reinterpret_cast<float4*>(out + (size_t)(r0 + 1) * HDIM + colBase);
        #pragma unroll
        for (int c4 = 0; c4 < 8; c4++)
            o1[c4] = make_float4(acc1[4*c4], acc1[4*c4+1], acc1[4*c4+2], acc1[4*c4+3]);
    }
}

// ---------------- aggregation: one warp per node, gather-only ----------------
// out[i] = relu(b + dis[i]^2 * hw[i] + sum_{e->i} dis[src]*dis[i]*hw[src])
__global__ void k_agg(const float* __restrict__ hw, const float* __restrict__ bias,
                      float* __restrict__ out) {
    int gw = (blockIdx.x * blockDim.x + threadIdx.x) >> 5;
    int lane = threadIdx.x & 31;
    if (gw >= N_NODES) return;

    float di = g_dis[gw];
    float b0 = __ldg(&bias[lane]);
    float b1 = __ldg(&bias[lane + 32]);

    // self loop: norm = dis[i]^2
    float acc0 = di * di * __ldg(&hw[(size_t)gw * HDIM + lane]);
    float acc1 = di * di * __ldg(&hw[(size_t)gw * HDIM + lane + 32]);

    int beg = g_rowoff[gw];
    int end = g_rowoff[gw + 1];
    int j = beg;
    for (; j + 3 < end; j += 4) {
        int s0 = g_csr[j], s1 = g_csr[j + 1], s2 = g_csr[j + 2], s3 = g_csr[j + 3];
        float n0 = di * g_dis[s0], n1 = di * g_dis[s1];
        float n2 = di * g_dis[s2], n3 = di * g_dis[s3];
        float a0 = __ldg(&hw[(size_t)s0 * HDIM + lane]);
        float a1 = __ldg(&hw[(size_t)s0 * HDIM + lane + 32]);
        float c0 = __ldg(&hw[(size_t)s1 * HDIM + lane]);
        float c1 = __ldg(&hw[(size_t)s1 * HDIM + lane + 32]);
        float d0 = __ldg(&hw[(size_t)s2 * HDIM + lane]);
        float d1 = __ldg(&hw[(size_t)s2 * HDIM + lane + 32]);
        float e0 = __ldg(&hw[(size_t)s3 * HDIM + lane]);
        float e1 = __ldg(&hw[(size_t)s3 * HDIM + lane + 32]);
        acc0 += n0 * a0 + n1 * c0 + n2 * d0 + n3 * e0;
        acc1 += n0 * a1 + n1 * c1 + n2 * d1 + n3 * e1;
    }
    for (; j < end; ++j) {
        int s = g_csr[j];
        float nw = di * g_dis[s];
        acc0 += nw * __ldg(&hw[(size_t)s * HDIM + lane]);
        acc1 += nw * __ldg(&hw[(size_t)s * HDIM + lane + 32]);
    }

    out[(size_t)gw * HDIM + lane]      = fmaxf(acc0 + b0, 0.f);
    out[(size_t)gw * HDIM + lane + 32] = fmaxf(acc1 + b1, 0.f);
}

// ---------------- mean pool over nodes ---------------------------------------
__global__ void k_pool(const float* __restrict__ h) {
    __shared__ float sh[256];
    int col = threadIdx.x & 63;
    int seg = threadIdx.x >> 6;     // 0..3
    float acc = 0.f;
    for (int r = blockIdx.x * 4 + seg; r < N_NODES; r += gridDim.x * 4)
        acc += h[(size_t)r * HDIM + col];
    sh[threadIdx.x] = acc;
    __syncthreads();
    if (threadIdx.x < 64) {
        float v = sh[threadIdx.x] + sh[threadIdx.x + 64] +
                  sh[threadIdx.x + 128] + sh[threadIdx.x + 192];
        atomicAdd(&g_pool[threadIdx.x], v);
    }
}

// ---------------- head: global MLP + fc1 + fc2 (tiny, 1 block) ---------------
__global__ void k_head(const float* __restrict__ gf,
                       const float* __restrict__ w_glob, const float* __restrict__ b_glob,
                       const float* __restrict__ w_fc1, const float* __restrict__ b_fc1,
                       const float* __restrict__ w_fc2, const float* __restrict__ b_fc2,
                       float* __restrict__ out) {
    __shared__ float xc[2 * HDIM];
    __shared__ float t1[HDIM];
    int t = threadIdx.x;

    xc[t] = g_pool[t] * (1.0f / (float)N_NODES);      // x_graph (mean)

    float a = b_glob[t];
    #pragma unroll
    for (int k = 0; k < FGLOB; k++) a += gf[k] * w_glob[k * HDIM + t];
    xc[HDIM + t] = fmaxf(a, 0.f);                     // x_global
    __syncthreads();

    float u = b_fc1[t];
    #pragma unroll 8
    for (int k = 0; k < 2 * HDIM; k++) u += xc[k] * w_fc1[k * HDIM + t];
    t1[t] = fmaxf(u, 0.f);
    __syncthreads();

    float o = b_fc2[t];
    #pragma unroll 8
    for (int k = 0; k < HDIM; k++) o += t1[k] * w_fc2[k * OUTDIM + t];
    out[t] = o;
}

// ---------------- launch ------------------------------------------------------
extern "C" void kernel_launch(void* const* d_in, const int* in_sizes, int n_in,
                              void* d_out, int out_size) {
    const float* x      = (const float*)d_in[0];
    const int*   ei     = (const int*)  d_in[1];   // [2,E]: first E = src, next E = dst
    const float* gf     = (const float*)d_in[2];
    const float* w_node = (const float*)d_in[3];
    const float* b_node = (const float*)d_in[4];
    const float* w_glob = (const float*)d_in[5];
    const float* b_glob = (const float*)d_in[6];
    const float* w_c[3] = {(const float*)d_in[7], (const float*)d_in[9],  (const float*)d_in[11]};
    const float* b_c[3] = {(const float*)d_in[8], (const float*)d_in[10], (const float*)d_in[12]};
    const float* w_fc1  = (const float*)d_in[13];
    const float* b_fc1  = (const float*)d_in[14];
    const float* w_fc2  = (const float*)d_in[15];
    const float* b_fc2  = (const float*)d_in[16];
    float* out = (float*)d_out;

    float *p_h, *p_hw;
    cudaGetSymbolAddress((void**)&p_h,  g_h);
    cudaGetSymbolAddress((void**)&p_hw, g_hw);

    const int TB = 256;
    // --- graph structure (CSR by dst) ---
    k_init <<<(N_NODES + TB - 1) / TB, TB>>>();
    k_count<<<(N_EDGES + TB - 1) / TB, TB>>>(ei + N_EDGES);
    k_dis  <<<(N_NODES + TB - 1) / TB, TB>>>();
    k_scan1<<<N_SCAN_BLOCKS, SCAN_BS>>>();
    k_scan2<<<1, 128>>>();
    k_scan3<<<(N_NODES + TB - 1) / TB, TB>>>();
    k_fill <<<(N_EDGES + TB - 1) / TB, TB>>>(ei, ei + N_EDGES);

    // --- node embedding: h = x @ w_node + b_node ---
    k_gemm<FNODE, true><<<(N_NODES + 255) / 256, 256>>>(x, w_node, b_node, p_h);

    // --- 3 GCN layers ---
    for (int l = 0; l < 3; l++) {
        k_gemm<HDIM, false><<<(N_NODES + 255) / 256, 256>>>(p_h, w_c[l], nullptr, p_hw);
        k_agg<<<(N_NODES * 32 + TB - 1) / TB, TB>>>(p_hw, b_c[l], p_h);
    }

    // --- pool + head ---
    k_pool<<<256, 256>>>(p_h);
    k_head<<<1, 64>>>(gf, w_glob, b_glob, w_fc1, b_fc1, w_fc2, b_fc2, out);
}

// round 2
// speedup vs baseline: 1.0414x; 1.0414x over previous
#include <cuda_runtime.h>
#include <cuda_bf16.h>

#define N_NODES 100000
#define N_EDGES 1600000
#define FNODE   32
#define FGLOB   16
#define HDIM    64
#define OUTDIM  64

#define SCAN_BS 1024
#define N_SCAN_BLOCKS ((N_NODES + SCAN_BS - 1) / SCAN_BS)   // 98

// ---------------- scratch (device globals: no allocations allowed) ----------
__device__ int   g_cnt[N_NODES];
__device__ int   g_cursor[N_NODES];
__device__ int   g_rowoff[N_NODES];          // block-local exclusive scan
__device__ int   g_bsum[N_SCAN_BLOCKS];      // exclusive block offsets
__device__ int   g_csr[N_EDGES];
__device__ float g_dis[N_NODES];
__device__ __align__(16) float g_h[(size_t)N_NODES * HDIM];
__device__ __align__(16) float g_hw[(size_t)N_NODES * HDIM];
__device__ float g_pool[HDIM];

// ---------------- init: zero counters, cursors, pool ------------------------
__global__ void k_init() {
    int i = blockIdx.x * blockDim.x + threadIdx.x;
    if (i < N_NODES) { g_cnt[i] = 0; g_cursor[i] = 0; }
    if (i < HDIM) g_pool[i] = 0.f;
}

// ---------------- degree count over dst --------------------------------------
__global__ void k_count(const int* __restrict__ dst) {
    int e = blockIdx.x * blockDim.x + threadIdx.x;
    if (e < N_EDGES) atomicAdd(&g_cnt[dst[e]], 1);
}

// ---------------- scan stage 1 (shuffle-based) + dis -------------------------
__global__ void k_scan1() {
    __shared__ int wsum[32];
    int tid = threadIdx.x;
    int i = blockIdx.x * SCAN_BS + tid;
    int v = (i < N_NODES) ? g_cnt[i] : 0;
    if (i < N_NODES) g_dis[i] = rsqrtf((float)(v + 1));

    int lane = tid & 31, w = tid >> 5;
    int s = v;
    #pragma unroll
    for (int o = 1; o < 32; o <<= 1) {
        int t = __shfl_up_sync(0xffffffffu, s, o);
        if (lane >= o) s += t;
    }
    if (lane == 31) wsum[w] = s;
    __syncthreads();
    if (w == 0) {
        int ws = wsum[lane];
        int t = ws;
        #pragma unroll
        for (int o = 1; o < 32; o <<= 1) {
            int u = __shfl_up_sync(0xffffffffu, t, o);
            if (lane >= o) t += u;
        }
        wsum[lane] = t - ws;                        // exclusive warp offsets
        if (lane == 31) g_bsum[blockIdx.x] = t;     // block total (raw)
    }
    __syncthreads();
    if (i < N_NODES) g_rowoff[i] = wsum[w] + s - v; // block-local exclusive
}

// ---------------- scan stage 2: exclusive-scan block totals in place ---------
__global__ void k_scan2() {
    __shared__ int wsum[4];
    int tid = threadIdx.x;                 // 128 threads
    int v = (tid < N_SCAN_BLOCKS) ? g_bsum[tid] : 0;
    int lane = tid & 31, w = tid >> 5;
    int s = v;
    #pragma unroll
    for (int o = 1; o < 32; o <<= 1) {
        int t = __shfl_up_sync(0xffffffffu, s, o);
        if (lane >= o) s += t;
    }
    if (lane == 31) wsum[w] = s;
    __syncthreads();
    int woff = 0;
    #pragma unroll
    for (int k = 0; k < 4; k++) if (k < w) woff += wsum[k];
    if (tid < N_SCAN_BLOCKS) g_bsum[tid] = woff + s - v;   // exclusive
}

// ---------------- CSR fill ----------------------------------------------------
__global__ void k_fill(const int* __restrict__ src, const int* __restrict__ dst) {
    int e = blockIdx.x * blockDim.x + threadIdx.x;
    if (e < N_EDGES) {
        int d = dst[e];
        int base = g_rowoff[d] + g_bsum[d >> 10];
        int pos = base + atomicAdd(&g_cursor[d], 1);
        g_csr[pos] = src[e];
    }
}

// ---------------- dense GEMM: out[N,64] = in[N,K] @ W[K,64] ------------------
// BIAS: add bias (embedding). SCALE: scale row r by dis[r] (conv layers).
template<int K, bool BIAS, bool SCALE>
__global__ void k_gemm(const float* __restrict__ in, const float* __restrict__ w,
                       const float* __restrict__ bias, float* __restrict__ out) {
    __shared__ float4 Ws4[K * 16];         // 64 cols = 16 float4 per k-row
    __shared__ float Bs[HDIM];
    int tid = threadIdx.x;
    for (int j = tid; j < K * 16; j += blockDim.x)
        Ws4[j] = reinterpret_cast<const float4*>(w)[j];
    if (BIAS && tid < HDIM) Bs[tid] = bias[tid];
    __syncthreads();

    int colBase = (tid & 1) * 32;
    int cb4 = colBase >> 2;                // 0 or 8
    int pair = tid >> 1;
    int r0 = blockIdx.x * 256 + pair * 2;
    if (r0 >= N_NODES) return;
    bool v1 = (r0 + 1 < N_NODES);

    float acc0[32], acc1[32];
    #pragma unroll
    for (int c = 0; c < 32; c++) { acc0[c] = 0.f; acc1[c] = 0.f; }

    const float4* xr0 = reinterpret_cast<const float4*>(in + (size_t)r0 * K);
    const float4* xr1 = reinterpret_cast<const float4*>(in + (size_t)(v1 ? r0 + 1 : r0) * K);

    #pragma unroll 4
    for (int k4 = 0; k4 < K / 4; ++k4) {
        float4 a = __ldg(&xr0[k4]);
        float4 b = __ldg(&xr1[k4]);
        const float av[4] = {a.x, a.y, a.z, a.w};
        const float bv[4] = {b.x, b.y, b.z, b.w};
        #pragma unroll
        for (int kk = 0; kk < 4; ++kk) {
            const float4* wrow = &Ws4[(k4 * 4 + kk) * 16 + cb4];
            float xa = av[kk], xb = bv[kk];
            #pragma unroll
            for (int c4 = 0; c4 < 8; c4++) {
                float4 wv = wrow[c4];
                acc0[c4*4+0] += xa * wv.x; acc1[c4*4+0] += xb * wv.x;
                acc0[c4*4+1] += xa * wv.y; acc1[c4*4+1] += xb * wv.y;
                acc0[c4*4+2] += xa * wv.z; acc1[c4*4+2] += xb * wv.z;
                acc0[c4*4+3] += xa * wv.w; acc1[c4*4+3] += xb * wv.w;
            }
        }
    }

    if (BIAS) {
        #pragma unroll
        for (int c = 0; c < 32; c++) { acc0[c] += Bs[colBase + c]; acc1[c] += Bs[colBase + c]; }
    }
    if (SCALE) {
        float s0 = g_dis[r0];
        float s1 = v1 ? g_dis[r0 + 1] : 0.f;
        #pragma unroll
        for (int c = 0; c < 32; c++) { acc0[c] *= s0; acc1[c] *= s1; }
    }

    float4* o0 = reinterpret_cast<float4*>(out + (size_t)r0 * HDIM + colBase);
    #pragma unroll
    for (int c4 = 0; c4 < 8; c4++)
        o0[c4] = make_float4(acc0[4*c4], acc0[4*c4+1], acc0[4*c4+2], acc0[4*c4+3]);
    if (v1) {
        float4* o1 = reinterpret_cast<float4*>(out + (size_t)(r0 + 1) * HDIM + colBase);
        #pragma unroll
        for (int c4 = 0; c4 < 8; c4++)
            o1[c4] = make_float4(acc1[4*c4], acc1[4*c4+1], acc1[4*c4+2], acc1[4*c4+3]);
    }
}

// ---------------- aggregation: one warp per node, pure gather-sum ------------
// hw rows are pre-scaled by dis[src]. out[i] = relu(dis[i]*sum + b)
__global__ void k_agg(const float* __restrict__ hw, const float* __restrict__ bias,
                      float* __restrict__ out) {
    int gw = (blockIdx.x * blockDim.x + threadIdx.x) >> 5;
    int lane = threadIdx.x & 31;
    if (gw >= N_NODES) return;

    const float2* hw2 = reinterpret_cast<const float2*>(hw);
    float2 b2 = __ldg(reinterpret_cast<const float2*>(bias) + lane);

    // self loop term (hw already includes dis[i])
    float2 acc = __ldg(&hw2[(size_t)gw * 32 + lane]);

    int beg = g_rowoff[gw] + g_bsum[gw >> 10];
    int cnt = g_cnt[gw];
    int end = beg + cnt;
    int j = beg;
    for (; j + 3 < end; j += 4) {
        int s0 = __ldg(&g_csr[j]);
        int s1 = __ldg(&g_csr[j + 1]);
        int s2 = __ldg(&g_csr[j + 2]);
        int s3 = __ldg(&g_csr[j + 3]);
        float2 a = __ldg(&hw2[(size_t)s0 * 32 + lane]);
        float2 b = __ldg(&hw2[(size_t)s1 * 32 + lane]);
        float2 c = __ldg(&hw2[(size_t)s2 * 32 + lane]);
        float2 d = __ldg(&hw2[(size_t)s3 * 32 + lane]);
        acc.x += a.x + b.x + c.x + d.x;
        acc.y += a.y + b.y + c.y + d.y;
    }
    for (; j < end; ++j) {
        int s = __ldg(&g_csr[j]);
        float2 a = __ldg(&hw2[(size_t)s * 32 + lane]);
        acc.x += a.x; acc.y += a.y;
    }

    float di = g_dis[gw];
    float2 o;
    o.x = fmaxf(fmaf(di, acc.x, b2.x), 0.f);
    o.y = fmaxf(fmaf(di, acc.y, b2.y), 0.f);
    reinterpret_cast<float2*>(out)[(size_t)gw * 32 + lane] = o;
}

// ---------------- mean pool over nodes ---------------------------------------
__global__ void k_pool(const float* __restrict__ h) {
    __shared__ float sh[256];
    int col = threadIdx.x & 63;
    int seg = threadIdx.x >> 6;     // 0..3
    float acc = 0.f;
    for (int r = blockIdx.x * 4 + seg; r < N_NODES; r += gridDim.x * 4)
        acc += h[(size_t)r * HDIM + col];
    sh[threadIdx.x] = acc;
    __syncthreads();
    if (threadIdx.x < 64) {
        float v = sh[threadIdx.x] + sh[threadIdx.x + 64] +
                  sh[threadIdx.x + 128] + sh[threadIdx.x + 192];
        atomicAdd(&g_pool[threadIdx.x], v);
    }
}

// ---------------- head: global MLP + fc1 + fc2 (tiny, 1 block) ---------------
__global__ void k_head(const float* __restrict__ gf,
                       const float* __restrict__ w_glob, const float* __restrict__ b_glob,
                       const float* __restrict__ w_fc1, const float* __restrict__ b_fc1,
                       const float* __restrict__ w_fc2, const float* __restrict__ b_fc2,
                       float* __restrict__ out) {
    __shared__ float xc[2 * HDIM];
    __shared__ float t1[HDIM];
    int t = threadIdx.x;

    xc[t] = g_pool[t] * (1.0f / (float)N_NODES);      // x_graph (mean)

    float a = b_glob[t];
    #pragma unroll
    for (int k = 0; k < FGLOB; k++) a += gf[k] * w_glob[k * HDIM + t];
    xc[HDIM + t] = fmaxf(a, 0.f);                     // x_global
    __syncthreads();

    float u = b_fc1[t];
    #pragma unroll 8
    for (int k = 0; k < 2 * HDIM; k++) u += xc[k] * w_fc1[k * HDIM + t];
    t1[t] = fmaxf(u, 0.f);
    __syncthreads();

    float o = b_fc2[t];
    #pragma unroll 8
    for (int k = 0; k < HDIM; k++) o += t1[k] * w_fc2[k * OUTDIM + t];
    out[t] = o;
}

// ---------------- launch ------------------------------------------------------
extern "C" void kernel_launch(void* const* d_in, const int* in_sizes, int n_in,
                              void* d_out, int out_size) {
    const float* x      = (const float*)d_in[0];
    const int*   ei     = (const int*)  d_in[1];   // [2,E]: first E = src, next E = dst
    const float* gf     = (const float*)d_in[2];
    const float* w_node = (const float*)d_in[3];
    const float* b_node = (const float*)d_in[4];
    const float* w_glob = (const float*)d_in[5];
    const float* b_glob = (const float*)d_in[6];
    const float* w_c[3] = {(const float*)d_in[7], (const float*)d_in[9],  (const float*)d_in[11]};
    const float* b_c[3] = {(const float*)d_in[8], (const float*)d_in[10], (const float*)d_in[12]};
    const float* w_fc1  = (const float*)d_in[13];
    const float* b_fc1  = (const float*)d_in[14];
    const float* w_fc2  = (const float*)d_in[15];
    const float* b_fc2  = (const float*)d_in[16];
    float* out = (float*)d_out;

    float *p_h, *p_hw;
    cudaGetSymbolAddress((void**)&p_h,  g_h);
    cudaGetSymbolAddress((void**)&p_hw, g_hw);

    // Lazily-created side stream + fork/join events (created outside capture on
    // the first, non-captured correctness call; reused thereafter — resource
    // reuse only, identical work every call).
    static cudaStream_t s_side = nullptr;
    static cudaEvent_t  s_evFork = nullptr, s_evJoin = nullptr;
    if (!s_side) {
        cudaStreamCreateWithFlags(&s_side, cudaStreamNonBlocking);
        cudaEventCreateWithFlags(&s_evFork, cudaEventDisableTiming);
        cudaEventCreateWithFlags(&s_evJoin, cudaEventDisableTiming);
    }

    const int TB = 256;

    // fork: CSR build chain on side stream
    cudaEventRecord(s_evFork, 0);
    cudaStreamWaitEvent(s_side, s_evFork, 0);
    k_init <<<(N_NODES + TB - 1) / TB, TB, 0, s_side>>>();
    k_count<<<(N_EDGES + TB - 1) / TB, TB, 0, s_side>>>(ei + N_EDGES);
    k_scan1<<<N_SCAN_BLOCKS, SCAN_BS, 0, s_side>>>();
    k_scan2<<<1, 128, 0, s_side>>>();
    k_fill <<<(N_EDGES + TB - 1) / TB, TB, 0, s_side>>>(ei, ei + N_EDGES);
    cudaEventRecord(s_evJoin, s_side);

    // main stream: node embedding GEMM (independent of CSR)
    k_gemm<FNODE, true, false><<<(N_NODES + 255) / 256, 256>>>(x, w_node, b_node, p_h);

    // join
    cudaStreamWaitEvent(0, s_evJoin, 0);

    // --- 3 GCN layers: hw = dis .* (h @ W); h = relu(dis .* gathersum(hw) + b)
    for (int l = 0; l < 3; l++) {
        k_gemm<HDIM, false, true><<<(N_NODES + 255) / 256, 256>>>(p_h, w_c[l], nullptr, p_hw);
        k_agg<<<(N_NODES * 32 + TB - 1) / TB, TB>>>(p_hw, b_c[l], p_h);
    }

    // --- pool + head ---
    k_pool<<<256, 256>>>(p_h);
    k_head<<<1, 64>>>(gf, w_glob, b_glob, w_fc1, b_fc1, w_fc2, b_fc2, out);
}

// round 3
// speedup vs baseline: 1.1309x; 1.0860x over previous
#include <cuda_runtime.h>
#include <cuda_fp16.h>
#include <cuda_bf16.h>

#define N_NODES 100000
#define N_EDGES 1600000
#define FNODE   32
#define FGLOB   16
#define HDIM    64
#define OUTDIM  64

#define SCAN_BS 1024
#define N_SCAN_BLOCKS ((N_NODES + SCAN_BS - 1) / SCAN_BS)   // 98

// ---------------- scratch (device globals: no allocations allowed) ----------
__device__ int   g_cnt[N_NODES];
__device__ int   g_cursor[N_NODES];
__device__ int   g_rowoff[N_NODES];          // block-local exclusive scan
__device__ int   g_bsum[N_SCAN_BLOCKS];      // exclusive block offsets
__device__ int   g_csr[N_EDGES];
__device__ float g_dis[N_NODES];
__device__ __align__(16) float  g_h[(size_t)N_NODES * HDIM];
__device__ __align__(16) __half g_hwh[(size_t)N_NODES * HDIM];   // fp16 messages, 128B/row
__device__ float g_pool[HDIM];

// ---------------- init: zero counters, cursors, pool ------------------------
__global__ void k_init() {
    int i = blockIdx.x * blockDim.x + threadIdx.x;
    if (i < N_NODES) { g_cnt[i] = 0; g_cursor[i] = 0; }
    if (i < HDIM) g_pool[i] = 0.f;
}

// ---------------- degree count over dst --------------------------------------
__global__ void k_count(const int* __restrict__ dst) {
    int e = blockIdx.x * blockDim.x + threadIdx.x;
    if (e < N_EDGES) atomicAdd(&g_cnt[dst[e]], 1);
}

// ---------------- scan stage 1 (shuffle-based) + dis -------------------------
__global__ void k_scan1() {
    __shared__ int wsum[32];
    int tid = threadIdx.x;
    int i = blockIdx.x * SCAN_BS + tid;
    int v = (i < N_NODES) ? g_cnt[i] : 0;
    if (i < N_NODES) g_dis[i] = rsqrtf((float)(v + 1));

    int lane = tid & 31, w = tid >> 5;
    int s = v;
    #pragma unroll
    for (int o = 1; o < 32; o <<= 1) {
        int t = __shfl_up_sync(0xffffffffu, s, o);
        if (lane >= o) s += t;
    }
    if (lane == 31) wsum[w] = s;
    __syncthreads();
    if (w == 0) {
        int ws = wsum[lane];
        int t = ws;
        #pragma unroll
        for (int o = 1; o < 32; o <<= 1) {
            int u = __shfl_up_sync(0xffffffffu, t, o);
            if (lane >= o) t += u;
        }
        wsum[lane] = t - ws;                        // exclusive warp offsets
        if (lane == 31) g_bsum[blockIdx.x] = t;     // block total (raw)
    }
    __syncthreads();
    if (i < N_NODES) g_rowoff[i] = wsum[w] + s - v; // block-local exclusive
}

// ---------------- scan stage 2: exclusive-scan block totals in place ---------
__global__ void k_scan2() {
    __shared__ int wsum[4];
    int tid = threadIdx.x;                 // 128 threads
    int v = (tid < N_SCAN_BLOCKS) ? g_bsum[tid] : 0;
    int lane = tid & 31, w = tid >> 5;
    int s = v;
    #pragma unroll
    for (int o = 1; o < 32; o <<= 1) {
        int t = __shfl_up_sync(0xffffffffu, s, o);
        if (lane >= o) s += t;
    }
    if (lane == 31) wsum[w] = s;
    __syncthreads();
    int woff = 0;
    #pragma unroll
    for (int k = 0; k < 4; k++) if (k < w) woff += wsum[k];
    if (tid < N_SCAN_BLOCKS) g_bsum[tid] = woff + s - v;   // exclusive
}

// ---------------- CSR fill ----------------------------------------------------
__global__ void k_fill(const int* __restrict__ src, const int* __restrict__ dst) {
    int e = blockIdx.x * blockDim.x + threadIdx.x;
    if (e < N_EDGES) {
        int d = dst[e];
        int base = g_rowoff[d] + g_bsum[d >> 10];
        int pos = base + atomicAdd(&g_cursor[d], 1);
        g_csr[pos] = src[e];
    }
}

// ---------------- dense GEMM: out[N,64] = in[N,K] @ W[K,64] ------------------
// H16OUT=false: fp32 out + bias (embedding).
// H16OUT=true : fp16 out, row scaled by dis[r] (conv layers' messages).
template<int K, bool H16OUT>
__global__ void k_gemm(const float* __restrict__ in, const float* __restrict__ w,
                       const float* __restrict__ bias,
                       float* __restrict__ outF, __half* __restrict__ outH) {
    __shared__ float4 Ws4[K * 16];         // 64 cols = 16 float4 per k-row
    __shared__ float Bs[HDIM];
    int tid = threadIdx.x;
    for (int j = tid; j < K * 16; j += blockDim.x)
        Ws4[j] = reinterpret_cast<const float4*>(w)[j];
    if (!H16OUT && tid < HDIM) Bs[tid] = bias[tid];
    __syncthreads();

    int colBase = (tid & 1) * 32;
    int cb4 = colBase >> 2;                // 0 or 8
    int pair = tid >> 1;
    int r0 = blockIdx.x * 256 + pair * 2;
    if (r0 >= N_NODES) return;
    bool v1 = (r0 + 1 < N_NODES);

    float acc0[32], acc1[32];
    #pragma unroll
    for (int c = 0; c < 32; c++) { acc0[c] = 0.f; acc1[c] = 0.f; }

    const float4* xr0 = reinterpret_cast<const float4*>(in + (size_t)r0 * K);
    const float4* xr1 = reinterpret_cast<const float4*>(in + (size_t)(v1 ? r0 + 1 : r0) * K);

    #pragma unroll 4
    for (int k4 = 0; k4 < K / 4; ++k4) {
        float4 a = __ldg(&xr0[k4]);
        float4 b = __ldg(&xr1[k4]);
        const float av[4] = {a.x, a.y, a.z, a.w};
        const float bv[4] = {b.x, b.y, b.z, b.w};
        #pragma unroll
        for (int kk = 0; kk < 4; ++kk) {
            const float4* wrow = &Ws4[(k4 * 4 + kk) * 16 + cb4];
            float xa = av[kk], xb = bv[kk];
            #pragma unroll
            for (int c4 = 0; c4 < 8; c4++) {
                float4 wv = wrow[c4];
                acc0[c4*4+0] += xa * wv.x; acc1[c4*4+0] += xb * wv.x;
                acc0[c4*4+1] += xa * wv.y; acc1[c4*4+1] += xb * wv.y;
                acc0[c4*4+2] += xa * wv.z; acc1[c4*4+2] += xb * wv.z;
                acc0[c4*4+3] += xa * wv.w; acc1[c4*4+3] += xb * wv.w;
            }
        }
    }

    if (H16OUT) {
        float s0 = g_dis[r0];
        float s1 = v1 ? g_dis[r0 + 1] : 0.f;
        __half2 hb0[16], hb1[16];
        #pragma unroll
        for (int c2 = 0; c2 < 16; c2++) {
            hb0[c2] = __floats2half2_rn(acc0[2*c2] * s0, acc0[2*c2+1] * s0);
            hb1[c2] = __floats2half2_rn(acc1[2*c2] * s1, acc1[2*c2+1] * s1);
        }
        uint4* o0 = reinterpret_cast<uint4*>(outH + (size_t)r0 * HDIM + colBase);
        const uint4* p0 = reinterpret_cast<const uint4*>(hb0);
        #pragma unroll
        for (int q = 0; q < 4; q++) o0[q] = p0[q];
        if (v1) {
            uint4* o1 = reinterpret_cast<uint4*>(outH + (size_t)(r0 + 1) * HDIM + colBase);
            const uint4* p1 = reinterpret_cast<const uint4*>(hb1);
            #pragma unroll
            for (int q = 0; q < 4; q++) o1[q] = p1[q];
        }
    } else {
        #pragma unroll
        for (int c = 0; c < 32; c++) { acc0[c] += Bs[colBase + c]; acc1[c] += Bs[colBase + c]; }
        float4* o0 = reinterpret_cast<float4*>(outF + (size_t)r0 * HDIM + colBase);
        #pragma unroll
        for (int c4 = 0; c4 < 8; c4++)
            o0[c4] = make_float4(acc0[4*c4], acc0[4*c4+1], acc0[4*c4+2], acc0[4*c4+3]);
        if (v1) {
            float4* o1 = reinterpret_cast<float4*>(outF + (size_t)(r0 + 1) * HDIM + colBase);
            #pragma unroll
            for (int c4 = 0; c4 < 8; c4++)
                o1[c4] = make_float4(acc1[4*c4], acc1[4*c4+1], acc1[4*c4+2], acc1[4*c4+3]);
        }
    }
}

// ---------------- aggregation: one warp per node, fp16 gather-sum ------------
// hwh rows (128B) are pre-scaled by dis[src]. out[i] = relu(dis[i]*sum + b)
__global__ void k_agg(const __half2* __restrict__ hw2, const float* __restrict__ bias,
                      float* __restrict__ out) {
    int gw = (blockIdx.x * blockDim.x + threadIdx.x) >> 5;
    int lane = threadIdx.x & 31;
    if (gw >= N_NODES) return;

    float2 b2 = __ldg(reinterpret_cast<const float2*>(bias) + lane);

    // self loop term (hwh already includes dis[i])
    float2 accA = __half22float2(__ldg(&hw2[(size_t)gw * 32 + lane]));
    float2 accB = make_float2(0.f, 0.f);

    int beg = g_rowoff[gw] + g_bsum[gw >> 10];
    int end = beg + g_cnt[gw];
    int j = beg;
    for (; j + 7 < end; j += 8) {
        int s0 = __ldg(&g_csr[j]);
        int s1 = __ldg(&g_csr[j + 1]);
        int s2 = __ldg(&g_csr[j + 2]);
        int s3 = __ldg(&g_csr[j + 3]);
        int s4 = __ldg(&g_csr[j + 4]);
        int s5 = __ldg(&g_csr[j + 5]);
        int s6 = __ldg(&g_csr[j + 6]);
        int s7 = __ldg(&g_csr[j + 7]);
        float2 v0 = __half22float2(__ldg(&hw2[(size_t)s0 * 32 + lane]));
        float2 v1 = __half22float2(__ldg(&hw2[(size_t)s1 * 32 + lane]));
        float2 v2 = __half22float2(__ldg(&hw2[(size_t)s2 * 32 + lane]));
        float2 v3 = __half22float2(__ldg(&hw2[(size_t)s3 * 32 + lane]));
        float2 v4 = __half22float2(__ldg(&hw2[(size_t)s4 * 32 + lane]));
        float2 v5 = __half22float2(__ldg(&hw2[(size_t)s5 * 32 + lane]));
        float2 v6 = __half22float2(__ldg(&hw2[(size_t)s6 * 32 + lane]));
        float2 v7 = __half22float2(__ldg(&hw2[(size_t)s7 * 32 + lane]));
        accA.x += v0.x + v1.x + v2.x + v3.x;
        accA.y += v0.y + v1.y + v2.y + v3.y;
        accB.x += v4.x + v5.x + v6.x + v7.x;
        accB.y += v4.y + v5.y + v6.y + v7.y;
    }
    for (; j < end; ++j) {
        int s = __ldg(&g_csr[j]);
        float2 v = __half22float2(__ldg(&hw2[(size_t)s * 32 + lane]));
        accA.x += v.x; accA.y += v.y;
    }

    float di = g_dis[gw];
    float2 o;
    o.x = fmaxf(fmaf(di, accA.x + accB.x, b2.x), 0.f);
    o.y = fmaxf(fmaf(di, accA.y + accB.y, b2.y), 0.f);
    reinterpret_cast<float2*>(out)[(size_t)gw * 32 + lane] = o;
}

// ---------------- mean pool over nodes ---------------------------------------
__global__ void k_pool(const float* __restrict__ h) {
    __shared__ float sh[256];
    int col = threadIdx.x & 63;
    int seg = threadIdx.x >> 6;     // 0..3
    float acc = 0.f;
    for (int r = blockIdx.x * 4 + seg; r < N_NODES; r += gridDim.x * 4)
        acc += h[(size_t)r * HDIM + col];
    sh[threadIdx.x] = acc;
    __syncthreads();
    if (threadIdx.x < 64) {
        float v = sh[threadIdx.x] + sh[threadIdx.x + 64] +
                  sh[threadIdx.x + 128] + sh[threadIdx.x + 192];
        atomicAdd(&g_pool[threadIdx.x], v);
    }
}

// ---------------- head: global MLP + fc1 + fc2 (tiny, 1 block) ---------------
__global__ void k_head(const float* __restrict__ gf,
                       const float* __restrict__ w_glob, const float* __restrict__ b_glob,
                       const float* __restrict__ w_fc1, const float* __restrict__ b_fc1,
                       const float* __restrict__ w_fc2, const float* __restrict__ b_fc2,
                       float* __restrict__ out) {
    __shared__ float xc[2 * HDIM];
    __shared__ float t1[HDIM];
    int t = threadIdx.x;

    xc[t] = g_pool[t] * (1.0f / (float)N_NODES);      // x_graph (mean)

    float a = b_glob[t];
    #pragma unroll
    for (int k = 0; k < FGLOB; k++) a += gf[k] * w_glob[k * HDIM + t];
    xc[HDIM + t] = fmaxf(a, 0.f);                     // x_global
    __syncthreads();

    float u = b_fc1[t];
    #pragma unroll 8
    for (int k = 0; k < 2 * HDIM; k++) u += xc[k] * w_fc1[k * HDIM + t];
    t1[t] = fmaxf(u, 0.f);
    __syncthreads();

    float o = b_fc2[t];
    #pragma unroll 8
    for (int k = 0; k < HDIM; k++) o += t1[k] * w_fc2[k * OUTDIM + t];
    out[t] = o;
}

// ---------------- launch ------------------------------------------------------
extern "C" void kernel_launch(void* const* d_in, const int* in_sizes, int n_in,
                              void* d_out, int out_size) {
    const float* x      = (const float*)d_in[0];
    const int*   ei     = (const int*)  d_in[1];   // [2,E]: first E = src, next E = dst
    const float* gf     = (const float*)d_in[2];
    const float* w_node = (const float*)d_in[3];
    const float* b_node = (const float*)d_in[4];
    const float* w_glob = (const float*)d_in[5];
    const float* b_glob = (const float*)d_in[6];
    const float* w_c[3] = {(const float*)d_in[7], (const float*)d_in[9],  (const float*)d_in[11]};
    const float* b_c[3] = {(const float*)d_in[8], (const float*)d_in[10], (const float*)d_in[12]};
    const float* w_fc1  = (const float*)d_in[13];
    const float* b_fc1  = (const float*)d_in[14];
    const float* w_fc2  = (const float*)d_in[15];
    const float* b_fc2  = (const float*)d_in[16];
    float* out = (float*)d_out;

    float  *p_h;
    __half *p_hwh;
    cudaGetSymbolAddress((void**)&p_h,   g_h);
    cudaGetSymbolAddress((void**)&p_hwh, g_hwh);

    // Lazily-created side stream + fork/join events (created on the first,
    // non-captured correctness call; reused thereafter).
    static cudaStream_t s_side = nullptr;
    static cudaEvent_t  s_evFork = nullptr, s_evJoin = nullptr;
    if (!s_side) {
        cudaStreamCreateWithFlags(&s_side, cudaStreamNonBlocking);
        cudaEventCreateWithFlags(&s_evFork, cudaEventDisableTiming);
        cudaEventCreateWithFlags(&s_evJoin, cudaEventDisableTiming);
    }

    const int TB = 256;

    // fork: CSR build chain on side stream
    cudaEventRecord(s_evFork, 0);
    cudaStreamWaitEvent(s_side, s_evFork, 0);
    k_init <<<(N_NODES + TB - 1) / TB, TB, 0, s_side>>>();
    k_count<<<(N_EDGES + TB - 1) / TB, TB, 0, s_side>>>(ei + N_EDGES);
    k_scan1<<<N_SCAN_BLOCKS, SCAN_BS, 0, s_side>>>();
    k_scan2<<<1, 128, 0, s_side>>>();
    k_fill <<<(N_EDGES + TB - 1) / TB, TB, 0, s_side>>>(ei, ei + N_EDGES);
    cudaEventRecord(s_evJoin, s_side);

    // main stream: node embedding GEMM, then layer-1 transform (neither needs CSR).
    // NOTE: layer-1 GEMM needs dis[] for its epilogue scale — but dis is written
    // by k_scan1 on the side stream. So it DOES depend on the CSR chain. Keep the
    // join before it; the embedding GEMM alone covers most of the chain.
    k_gemm<FNODE, false><<<(N_NODES + 255) / 256, 256>>>(x, w_node, b_node, p_h, nullptr);

    // join
    cudaStreamWaitEvent(0, s_evJoin, 0);

    // --- 3 GCN layers: hwh = fp16(dis .* (h @ W)); h = relu(dis .* gathersum + b)
    for (int l = 0; l < 3; l++) {
        k_gemm<HDIM, true><<<(N_NODES + 255) / 256, 256>>>(p_h, w_c[l], nullptr, nullptr, p_hwh);
        k_agg<<<(N_NODES * 32 + TB - 1) / TB, TB>>>((const __half2*)p_hwh, b_c[l], p_h);
    }

    // --- pool + head ---
    k_pool<<<256, 256>>>(p_h);
    k_head<<<1, 64>>>(gf, w_glob, b_glob, w_fc1, b_fc1, w_fc2, b_fc2, out);
}

// round 4
// speedup vs baseline: 1.6494x; 1.4586x over previous
#include <cuda_runtime.h>
#include <cuda_fp16.h>
#include <cuda_bf16.h>
#include <cstdint>

#define N_NODES 100000
#define N_EDGES 1600000
#define FNODE   32
#define FGLOB   16
#define HDIM    64
#define OUTDIM  64

#define SCAN_BS 1024
#define N_SCAN_BLOCKS ((N_NODES + SCAN_BS - 1) / SCAN_BS)   // 98

// ---------------- scratch (device globals: no allocations allowed) ----------
__device__ int   g_cnt[N_NODES];
__device__ int   g_cursor[N_NODES];
__device__ int   g_rowoff[N_NODES];          // block-local exclusive scan
__device__ int   g_bsum[N_SCAN_BLOCKS];      // exclusive block offsets
__device__ int   g_csr[N_EDGES];
__device__ float g_dis[N_NODES];
__device__ __align__(16) __half g_hf[(size_t)N_NODES * HDIM];    // node features fp16
__device__ __align__(16) __half g_hwh[(size_t)N_NODES * HDIM];   // messages fp16, 128B/row
__device__ float g_pool[HDIM];

// ---------------- init ---------------------------------------------------------
__global__ void k_init() {
    int i = blockIdx.x * blockDim.x + threadIdx.x;
    if (i < N_NODES) { g_cnt[i] = 0; g_cursor[i] = 0; }
    if (i < HDIM) g_pool[i] = 0.f;
}

// ---------------- degree count over dst ----------------------------------------
__global__ void k_count(const int* __restrict__ dst) {
    int e = blockIdx.x * blockDim.x + threadIdx.x;
    if (e < N_EDGES) atomicAdd(&g_cnt[dst[e]], 1);
}

// ---------------- scan stage 1 (shuffle-based) + dis ----------------------------
__global__ void k_scan1() {
    __shared__ int wsum[32];
    int tid = threadIdx.x;
    int i = blockIdx.x * SCAN_BS + tid;
    int v = (i < N_NODES) ? g_cnt[i] : 0;
    if (i < N_NODES) g_dis[i] = rsqrtf((float)(v + 1));

    int lane = tid & 31, w = tid >> 5;
    int s = v;
    #pragma unroll
    for (int o = 1; o < 32; o <<= 1) {
        int t = __shfl_up_sync(0xffffffffu, s, o);
        if (lane >= o) s += t;
    }
    if (lane == 31) wsum[w] = s;
    __syncthreads();
    if (w == 0) {
        int ws = wsum[lane];
        int t = ws;
        #pragma unroll
        for (int o = 1; o < 32; o <<= 1) {
            int u = __shfl_up_sync(0xffffffffu, t, o);
            if (lane >= o) t += u;
        }
        wsum[lane] = t - ws;
        if (lane == 31) g_bsum[blockIdx.x] = t;
    }
    __syncthreads();
    if (i < N_NODES) g_rowoff[i] = wsum[w] + s - v;
}

// ---------------- scan stage 2 --------------------------------------------------
__global__ void k_scan2() {
    __shared__ int wsum[4];
    int tid = threadIdx.x;                 // 128 threads
    int v = (tid < N_SCAN_BLOCKS) ? g_bsum[tid] : 0;
    int lane = tid & 31, w = tid >> 5;
    int s = v;
    #pragma unroll
    for (int o = 1; o < 32; o <<= 1) {
        int t = __shfl_up_sync(0xffffffffu, s, o);
        if (lane >= o) s += t;
    }
    if (lane == 31) wsum[w] = s;
    __syncthreads();
    int woff = 0;
    #pragma unroll
    for (int k = 0; k < 4; k++) if (k < w) woff += wsum[k];
    if (tid < N_SCAN_BLOCKS) g_bsum[tid] = woff + s - v;
}

// ---------------- CSR fill ------------------------------------------------------
__global__ void k_fill(const int* __restrict__ src, const int* __restrict__ dst) {
    int e = blockIdx.x * blockDim.x + threadIdx.x;
    if (e < N_EDGES) {
        int d = dst[e];
        int base = g_rowoff[d] + g_bsum[d >> 10];
        int pos = base + atomicAdd(&g_cursor[d], 1);
        g_csr[pos] = src[e];
    }
}

// ---------------- embedding GEMM: hf[N,64] = fp16(x[N,32] @ W + b) --------------
__global__ void k_embed(const float* __restrict__ in, const float* __restrict__ w,
                        const float* __restrict__ bias, __half* __restrict__ out) {
    __shared__ float4 Ws4[FNODE * 16];
    __shared__ float Bs[HDIM];
    int tid = threadIdx.x;
    for (int j = tid; j < FNODE * 16; j += blockDim.x)
        Ws4[j] = reinterpret_cast<const float4*>(w)[j];
    if (tid < HDIM) Bs[tid] = bias[tid];
    __syncthreads();

    int colBase = (tid & 1) * 32;
    int cb4 = colBase >> 2;
    int pair = tid >> 1;
    int r0 = blockIdx.x * 256 + pair * 2;
    if (r0 >= N_NODES) return;
    bool v1 = (r0 + 1 < N_NODES);

    float acc0[32], acc1[32];
    #pragma unroll
    for (int c = 0; c < 32; c++) { acc0[c] = 0.f; acc1[c] = 0.f; }

    const float4* xr0 = reinterpret_cast<const float4*>(in + (size_t)r0 * FNODE);
    const float4* xr1 = reinterpret_cast<const float4*>(in + (size_t)(v1 ? r0 + 1 : r0) * FNODE);

    #pragma unroll
    for (int k4 = 0; k4 < FNODE / 4; ++k4) {
        float4 a = __ldg(&xr0[k4]);
        float4 b = __ldg(&xr1[k4]);
        const float av[4] = {a.x, a.y, a.z, a.w};
        const float bv[4] = {b.x, b.y, b.z, b.w};
        #pragma unroll
        for (int kk = 0; kk < 4; ++kk) {
            const float4* wrow = &Ws4[(k4 * 4 + kk) * 16 + cb4];
            float xa = av[kk], xb = bv[kk];
            #pragma unroll
            for (int c4 = 0; c4 < 8; c4++) {
                float4 wv = wrow[c4];
                acc0[c4*4+0] += xa * wv.x; acc1[c4*4+0] += xb * wv.x;
                acc0[c4*4+1] += xa * wv.y; acc1[c4*4+1] += xb * wv.y;
                acc0[c4*4+2] += xa * wv.z; acc1[c4*4+2] += xb * wv.z;
                acc0[c4*4+3] += xa * wv.w; acc1[c4*4+3] += xb * wv.w;
            }
        }
    }

    __half2 hb0[16], hb1[16];
    #pragma unroll
    for (int c2 = 0; c2 < 16; c2++) {
        hb0[c2] = __floats2half2_rn(acc0[2*c2] + Bs[colBase + 2*c2],
                                    acc0[2*c2+1] + Bs[colBase + 2*c2 + 1]);
        hb1[c2] = __floats2half2_rn(acc1[2*c2] + Bs[colBase + 2*c2],
                                    acc1[2*c2+1] + Bs[colBase + 2*c2 + 1]);
    }
    uint4* o0 = reinterpret_cast<uint4*>(out + (size_t)r0 * HDIM + colBase);
    const uint4* p0 = reinterpret_cast<const uint4*>(hb0);
    #pragma unroll
    for (int q = 0; q < 4; q++) o0[q] = p0[q];
    if (v1) {
        uint4* o1 = reinterpret_cast<uint4*>(out + (size_t)(r0 + 1) * HDIM + colBase);
        const uint4* p1 = reinterpret_cast<const uint4*>(hb1);
        #pragma unroll
        for (int q = 0; q < 4; q++) o1[q] = p1[q];
    }
}

// ---------------- HMMA conv transform: hwh = fp16(dis .* (hf @ W)) --------------
// Block: 256 threads = 8 warps, 128 rows. Warp computes 16x64 via m16n8k16 mma.
#define APITCH 72   // halves; 144B rows: 16B-aligned, conflict-free ldmatrix
__global__ void k_hmma(const __half* __restrict__ hin, const float* __restrict__ w,
                       __half* __restrict__ outH) {
    __shared__ __half Wsm[HDIM * APITCH];
    __shared__ __half Asm[128 * APITCH];
    int tid = threadIdx.x;
    int lane = tid & 31, wid = tid >> 5;
    int rowBase = blockIdx.x * 128;

    // stage W (fp32 -> fp16)
    for (int i = tid; i < HDIM * HDIM; i += 256) {
        int r = i >> 6, c = i & 63;
        Wsm[r * APITCH + c] = __float2half(w[i]);
    }
    // stage A rows (uint2 = 4 halves, 8B aligned)
    for (int i = tid; i < 128 * 16; i += 256) {
        int r = i >> 4, c4 = i & 15;
        int gr = rowBase + r;
        uint2 v = make_uint2(0u, 0u);
        if (gr < N_NODES)
            v = *reinterpret_cast<const uint2*>(hin + (size_t)gr * HDIM + c4 * 4);
        *reinterpret_cast<uint2*>(&Asm[r * APITCH + c4 * 4]) = v;
    }
    __syncthreads();

    float acc[8][4];
    #pragma unroll
    for (int j = 0; j < 8; j++)
        #pragma unroll
        for (int q = 0; q < 4; q++) acc[j][q] = 0.f;

    uint32_t aAddr = (uint32_t)__cvta_generic_to_shared(
        &Asm[(wid * 16 + (lane & 15)) * APITCH + (lane >> 4) * 8]);
    uint32_t bAddr = (uint32_t)__cvta_generic_to_shared(
        &Wsm[(lane & 15) * APITCH]);

    #pragma unroll
    for (int k = 0; k < 4; k++) {
        uint32_t a0, a1, a2, a3;
        asm volatile("ldmatrix.sync.aligned.m8n8.x4.shared.b16 {%0,%1,%2,%3}, [%4];\n"
                     : "=r"(a0), "=r"(a1), "=r"(a2), "=r"(a3)
                     : "r"(aAddr + k * 16 * 2));
        #pragma unroll
        for (int j = 0; j < 8; j++) {
            uint32_t b0, b1;
            asm volatile("ldmatrix.sync.aligned.m8n8.x2.trans.shared.b16 {%0,%1}, [%2];\n"
                         : "=r"(b0), "=r"(b1)
                         : "r"(bAddr + (k * 16 * APITCH + j * 8) * 2));
            asm volatile("mma.sync.aligned.m16n8k16.row.col.f32.f16.f16.f32 "
                         "{%0,%1,%2,%3}, {%4,%5,%6,%7}, {%8,%9}, {%0,%1,%2,%3};\n"
                         : "+f"(acc[j][0]), "+f"(acc[j][1]), "+f"(acc[j][2]), "+f"(acc[j][3])
                         : "r"(a0), "r"(a1), "r"(a2), "r"(a3), "r"(b0), "r"(b1));
        }
    }

    // epilogue: scale rows by dis, convert fp16, store
    int g = lane >> 2, t2 = (lane & 3) * 2;
    int r0 = rowBase + wid * 16 + g;
    int r1 = r0 + 8;
    float d0 = (r0 < N_NODES) ? g_dis[r0] : 0.f;
    float d1 = (r1 < N_NODES) ? g_dis[r1] : 0.f;
    if (r0 < N_NODES) {
        __half* o = outH + (size_t)r0 * HDIM + t2;
        #pragma unroll
        for (int j = 0; j < 8; j++)
            *reinterpret_cast<__half2*>(o + j * 8) =
                __floats2half2_rn(acc[j][0] * d0, acc[j][1] * d0);
    }
    if (r1 < N_NODES) {
        __half* o = outH + (size_t)r1 * HDIM + t2;
        #pragma unroll
        for (int j = 0; j < 8; j++)
            *reinterpret_cast<__half2*>(o + j * 8) =
                __floats2half2_rn(acc[j][2] * d1, acc[j][3] * d1);
    }
}

// ---------------- aggregation: one warp per node, fp16 gather-sum ---------------
// hwh rows (128B) pre-scaled by dis[src]. hf[i] = fp16(relu(dis[i]*sum + b))
__global__ void k_agg(const __half2* __restrict__ hw2, const float* __restrict__ bias,
                      __half2* __restrict__ outh) {
    int gw = (blockIdx.x * blockDim.x + threadIdx.x) >> 5;
    int lane = threadIdx.x & 31;
    if (gw >= N_NODES) return;

    float2 b2 = __ldg(reinterpret_cast<const float2*>(bias) + lane);

    float2 accA = __half22float2(__ldg(&hw2[(size_t)gw * 32 + lane]));   // self loop
    float2 accB = make_float2(0.f, 0.f);

    int beg = g_rowoff[gw] + g_bsum[gw >> 10];
    int end = beg + g_cnt[gw];
    int j = beg;
    for (; j + 7 < end; j += 8) {
        int s0 = __ldg(&g_csr[j]);
        int s1 = __ldg(&g_csr[j + 1]);
        int s2 = __ldg(&g_csr[j + 2]);
        int s3 = __ldg(&g_csr[j + 3]);
        int s4 = __ldg(&g_csr[j + 4]);
        int s5 = __ldg(&g_csr[j + 5]);
        int s6 = __ldg(&g_csr[j + 6]);
        int s7 = __ldg(&g_csr[j + 7]);
        float2 v0 = __half22float2(__ldg(&hw2[(size_t)s0 * 32 + lane]));
        float2 v1 = __half22float2(__ldg(&hw2[(size_t)s1 * 32 + lane]));
        float2 v2 = __half22float2(__ldg(&hw2[(size_t)s2 * 32 + lane]));
        float2 v3 = __half22float2(__ldg(&hw2[(size_t)s3 * 32 + lane]));
        float2 v4 = __half22float2(__ldg(&hw2[(size_t)s4 * 32 + lane]));
        float2 v5 = __half22float2(__ldg(&hw2[(size_t)s5 * 32 + lane]));
        float2 v6 = __half22float2(__ldg(&hw2[(size_t)s6 * 32 + lane]));
        float2 v7 = __half22float2(__ldg(&hw2[(size_t)s7 * 32 + lane]));
        accA.x += v0.x + v1.x + v2.x + v3.x;
        accA.y += v0.y + v1.y + v2.y + v3.y;
        accB.x += v4.x + v5.x + v6.x + v7.x;
        accB.y += v4.y + v5.y + v6.y + v7.y;
    }
    for (; j < end; ++j) {
        int s = __ldg(&g_csr[j]);
        float2 v = __half22float2(__ldg(&hw2[(size_t)s * 32 + lane]));
        accA.x += v.x; accA.y += v.y;
    }

    float di = g_dis[gw];
    float ox = fmaxf(fmaf(di, accA.x + accB.x, b2.x), 0.f);
    float oy = fmaxf(fmaf(di, accA.y + accB.y, b2.y), 0.f);
    outh[(size_t)gw * 32 + lane] = __floats2half2_rn(ox, oy);
}

// ---------------- mean pool over nodes (fp16 input) ------------------------------
__global__ void k_pool(const __half2* __restrict__ h2) {
    __shared__ float2 sh[256];
    int c = threadIdx.x & 31;       // half2 column
    int seg = threadIdx.x >> 5;     // 0..7
    float2 acc = make_float2(0.f, 0.f);
    for (int r = blockIdx.x * 8 + seg; r < N_NODES; r += gridDim.x * 8) {
        float2 v = __half22float2(h2[(size_t)r * 32 + c]);
        acc.x += v.x; acc.y += v.y;
    }
    sh[threadIdx.x] = acc;
    __syncthreads();
    if (threadIdx.x < 32) {
        float2 s = sh[c];
        #pragma unroll
        for (int k = 1; k < 8; k++) {
            s.x += sh[k * 32 + c].x;
            s.y += sh[k * 32 + c].y;
        }
        atomicAdd(&g_pool[2 * c],     s.x);
        atomicAdd(&g_pool[2 * c + 1], s.y);
    }
}

// ---------------- head ------------------------------------------------------------
__global__ void k_head(const float* __restrict__ gf,
                       const float* __restrict__ w_glob, const float* __restrict__ b_glob,
                       const float* __restrict__ w_fc1, const float* __restrict__ b_fc1,
                       const float* __restrict__ w_fc2, const float* __restrict__ b_fc2,
                       float* __restrict__ out) {
    __shared__ float xc[2 * HDIM];
    __shared__ float t1[HDIM];
    int t = threadIdx.x;

    xc[t] = g_pool[t] * (1.0f / (float)N_NODES);

    float a = b_glob[t];
    #pragma unroll
    for (int k = 0; k < FGLOB; k++) a += gf[k] * w_glob[k * HDIM + t];
    xc[HDIM + t] = fmaxf(a, 0.f);
    __syncthreads();

    float u = b_fc1[t];
    #pragma unroll 8
    for (int k = 0; k < 2 * HDIM; k++) u += xc[k] * w_fc1[k * HDIM + t];
    t1[t] = fmaxf(u, 0.f);
    __syncthreads();

    float o = b_fc2[t];
    #pragma unroll 8
    for (int k = 0; k < HDIM; k++) o += t1[k] * w_fc2[k * OUTDIM + t];
    out[t] = o;
}

// ---------------- launch ------------------------------------------------------
extern "C" void kernel_launch(void* const* d_in, const int* in_sizes, int n_in,
                              void* d_out, int out_size) {
    const float* x      = (const float*)d_in[0];
    const int*   ei     = (const int*)  d_in[1];   // [2,E]: first E = src, next E = dst
    const float* gf     = (const float*)d_in[2];
    const float* w_node = (const float*)d_in[3];
    const float* b_node = (const float*)d_in[4];
    const float* w_glob = (const float*)d_in[5];
    const float* b_glob = (const float*)d_in[6];
    const float* w_c[3] = {(const float*)d_in[7], (const float*)d_in[9],  (const float*)d_in[11]};
    const float* b_c[3] = {(const float*)d_in[8], (const float*)d_in[10], (const float*)d_in[12]};
    const float* w_fc1  = (const float*)d_in[13];
    const float* b_fc1  = (const float*)d_in[14];
    const float* w_fc2  = (const float*)d_in[15];
    const float* b_fc2  = (const float*)d_in[16];
    float* out = (float*)d_out;

    __half *p_hf, *p_hwh;
    cudaGetSymbolAddress((void**)&p_hf,  g_hf);
    cudaGetSymbolAddress((void**)&p_hwh, g_hwh);

    static cudaStream_t s_side = nullptr;
    static cudaEvent_t  s_evFork = nullptr, s_evDis = nullptr, s_evFill = nullptr;
    if (!s_side) {
        cudaStreamCreateWithFlags(&s_side, cudaStreamNonBlocking);
        cudaEventCreateWithFlags(&s_evFork, cudaEventDisableTiming);
        cudaEventCreateWithFlags(&s_evDis,  cudaEventDisableTiming);
        cudaEventCreateWithFlags(&s_evFill, cudaEventDisableTiming);
    }

    const int TB = 256;

    // fork: CSR build chain on side stream
    cudaEventRecord(s_evFork, 0);
    cudaStreamWaitEvent(s_side, s_evFork, 0);
    k_init <<<(N_NODES + TB - 1) / TB, TB, 0, s_side>>>();
    k_count<<<(N_EDGES + TB - 1) / TB, TB, 0, s_side>>>(ei + N_EDGES);
    k_scan1<<<N_SCAN_BLOCKS, SCAN_BS, 0, s_side>>>();           // writes dis
    cudaEventRecord(s_evDis, s_side);
    k_scan2<<<1, 128, 0, s_side>>>();
    k_fill <<<(N_EDGES + TB - 1) / TB, TB, 0, s_side>>>(ei, ei + N_EDGES);
    cudaEventRecord(s_evFill, s_side);

    // main: embedding (no deps)
    k_embed<<<(N_NODES + 255) / 256, 256>>>(x, w_node, b_node, p_hf);

    const int HG = (N_NODES + 127) / 128;   // 782 blocks

    // layer 1 transform needs only dis
    cudaStreamWaitEvent(0, s_evDis, 0);
    k_hmma<<<HG, 256>>>(p_hf, w_c[0], p_hwh);
    // agg needs CSR
    cudaStreamWaitEvent(0, s_evFill, 0);
    k_agg<<<(N_NODES * 32 + TB - 1) / TB, TB>>>((const __half2*)p_hwh, b_c[0], (__half2*)p_hf);

    for (int l = 1; l < 3; l++) {
        k_hmma<<<HG, 256>>>(p_hf, w_c[l], p_hwh);
        k_agg<<<(N_NODES * 32 + TB - 1) / TB, TB>>>((const __half2*)p_hwh, b_c[l], (__half2*)p_hf);
    }

    // pool + head
    k_pool<<<256, 256>>>((const __half2*)p_hf);
    k_head<<<1, 64>>>(gf, w_glob, b_glob, w_fc1, b_fc1, w_fc2, b_fc2, out);
}